// round 16
// baseline (speedup 1.0000x reference)
#include <cuda_runtime.h>
#include <cuda_fp16.h>
#include <cstdint>

// ---------------------------------------------------------------------------
// Dcls1d via mma.sync (HMMA) fp16 GEMM, ACTIVE-d COMPACTION.
//   out[b,o,t] = bias[o] + sum_{d,i} K2[d,o,i] * x[b,i,t+d-16]
//   K2 and X single fp16 (validated error ~2.9e-4 rel l2). fp32 accum.
// R16: 64x64 warp tile (8 warps, 256 thr) -> 128 B/MMA smem traffic
//      (was 192) -> crossbar no longer co-limits. 3-slot A pipeline,
//      wait_group<=1, group-local A sync (2 groups x 128 thr).
// ---------------------------------------------------------------------------

#define B_   8
#define C_   256
#define T_   2048
#define O_   256
#define DKS_ 33
#define KC_  16
#define TP_  2080   // 16 + 2048 + 16 padded time rows

__device__ __align__(16) __half g_Kh[DKS_ * O_ * C_];   // [d][o][i], fp16
__device__ __align__(16) __half g_Xh[B_ * TP_ * C_];    // [b][t+16][i], fp16
__device__ unsigned long long g_maskblk[O_];            // per-o nonzero mask

// ---- PTX helpers -----------------------------------------------------------
__device__ __forceinline__ uint32_t smem_u32(const void* p) {
    uint32_t a;
    asm("{ .reg .u64 t; cvta.to.shared.u64 t, %1; cvt.u32.u64 %0, t; }"
        : "=r"(a) : "l"(p));
    return a;
}
__device__ __forceinline__ void cpa16(uint32_t dst, const void* src) {
    asm volatile("cp.async.ca.shared.global [%0], [%1], 16;" :: "r"(dst), "l"(src));
}
#define CP_COMMIT() asm volatile("cp.async.commit_group;" ::: "memory")
#define CP_WAIT0()  asm volatile("cp.async.wait_group 0;" ::: "memory")
#define CP_WAIT1()  asm volatile("cp.async.wait_group 1;" ::: "memory")
#define GROUP_BAR(id) asm volatile("bar.sync %0, 128;" :: "r"(id) : "memory")

__device__ __forceinline__ void ldmx4(uint32_t* r, uint32_t addr) {
    asm volatile("ldmatrix.sync.aligned.m8n8.x4.shared.b16 {%0,%1,%2,%3}, [%4];"
                 : "=r"(r[0]), "=r"(r[1]), "=r"(r[2]), "=r"(r[3]) : "r"(addr));
}
#define MMA(dv, a, b0v, b1v)                                                   \
    asm volatile("mma.sync.aligned.m16n8k16.row.col.f32.f16.f16.f32 "          \
                 "{%0,%1,%2,%3},{%4,%5,%6,%7},{%8,%9},{%0,%1,%2,%3};"          \
                 : "+f"((dv)[0]), "+f"((dv)[1]), "+f"((dv)[2]), "+f"((dv)[3])  \
                 : "r"((a)[0]), "r"((a)[1]), "r"((a)[2]), "r"((a)[3]),         \
                   "r"(b0v), "r"(b1v))

// ---------------------------------------------------------------------------
// Fused prep: blocks [0,4096) x transpose+fp16; [4096,4352) build K2.
// ---------------------------------------------------------------------------
__global__ void prep(const float* __restrict__ x,
                     const float* __restrict__ w,
                     const float* __restrict__ P) {
    __shared__ float sm[32][33];
    __shared__ unsigned long long s_m[8];
    const int tid = threadIdx.x;

    if (blockIdx.x < 4096) {
        int blk = blockIdx.x;
        int t0 = (blk & 63) * 32;
        int i0 = ((blk >> 6) & 7) * 32;
        int b  = blk >> 9;
        int tl = tid & 31, th = tid >> 5;

        if ((blk & 63) == 0) {   // zero pads
#pragma unroll
            for (int k = 0; k < 2; ++k) {
                int e = tid + k * 256;
                int r = e >> 5, cc = e & 31;
                g_Xh[((size_t)b * TP_ + r) * C_ + i0 + cc] = __float2half(0.f);
                g_Xh[((size_t)b * TP_ + (TP_ - 16 + r)) * C_ + i0 + cc] = __float2half(0.f);
            }
        }
#pragma unroll
        for (int k = 0; k < 4; ++k) {
            int i = i0 + th + k * 8;
            sm[th + k * 8][tl] = x[((size_t)b * C_ + i) * T_ + t0 + tl];
        }
        __syncthreads();
#pragma unroll
        for (int k = 0; k < 4; ++k) {
            int t = t0 + th + k * 8;
            g_Xh[((size_t)b * TP_ + t + 16) * C_ + i0 + tl] =
                __float2half(sm[tl][th + k * 8]);
        }
    } else {
        // ---- build_k2 (gather form, no local memory) ----
        int bk = blockIdx.x - 4096;               // out-channel o
        int oi = bk * 256 + tid;                  // tid = input channel i
        const float* Prow  = P + (size_t)oi * KC_;
        const float* P0row = P + (size_t)tid * KC_;  // out-channel 0 (frac src)
        const float* Wrow  = w + (size_t)oi * KC_;

        int   pi[KC_];
        float c1[KC_], c2[KC_];
#pragma unroll
        for (int k = 0; k < KC_; ++k) {
            float pp  = Prow[k] + 16.f;
            pi[k]     = (int)floorf(pp);
            float pp0 = P0row[k] + 16.f;
            float fr  = pp0 - floorf(pp0);
            float wv  = Wrow[k];
            c1[k] = wv * (1.f - fr);
            c2[k] = wv * fr;
        }
        unsigned long long bits = 0ull;
#pragma unroll
        for (int d = 0; d < DKS_; ++d) {
            float v = 0.f;
#pragma unroll
            for (int k = 0; k < KC_; ++k) {
                if (pi[k] == d)     v += c1[k];
                if (pi[k] + 1 == d) v += c2[k];
            }
            if (v != 0.f) bits |= 1ull << d;
            g_Kh[(size_t)(d * O_ + bk) * C_ + tid] = __float2half(v);
        }
#pragma unroll
        for (int s = 16; s > 0; s >>= 1)
            bits |= __shfl_xor_sync(0xffffffffu, bits, s);
        if ((tid & 31) == 0) s_m[tid >> 5] = bits;
        __syncthreads();
        if (tid == 0) {
            unsigned long long m = 0ull;
#pragma unroll
            for (int q = 0; q < 8; ++q) m |= s_m[q];
            g_maskblk[bk] = m;
        }
    }
}

// ---------------------------------------------------------------------------
// GEMM kernel.
// Block: 128 o x 256 t, 256 threads (8 warps: 2M x 4N, warp = 64 o x 64 t).
// ic-chunk = 128 i (2 chunks). smem rows 272B (conflict-free LDSM).
//   A (K2[d]): 128 x 128 i fp16, 3 slots; wm-group (128 thr) stages its 64 rows.
//   X: 288 x 128 i fp16 (per-ic, block barrier).
// cp.async depth 2 (wait_group<=1): A(j+1) in flight during compute(j).
// ---------------------------------------------------------------------------
#define ROWB   272u
#define A_TS   34816u      // one A slot (128*272)
#define X_OFF  (3u * 34816u)        // 104448
#define X_TS   78336u      // X tensor (288*272)
#define DSMEM  (104448u + 78336u + 128u)   // ~183 KB

__device__ __forceinline__ void stage_A_grp(uint32_t A0, int d, int slot,
                                            int o0, int ic, int wm, int gt) {
    uint32_t Ab = A0 + (uint32_t)slot * A_TS;
#pragma unroll
    for (int k = 0; k < 8; ++k) {
        int idx = gt + k * 128;                  // 1024 chunks (64r x 16c)
        int r   = (idx >> 4) & 63;
        int c   = idx & 15;
        int row = wm * 64 + r;
        const __half* src = g_Kh
            + ((size_t)(d * 256 + o0 + row) * 256 + ic * 128 + c * 8);
        cpa16(Ab + row * ROWB + c * 16, src);
    }
}

__global__ __launch_bounds__(256, 1)
void conv_mma(const float* __restrict__ bias, float* __restrict__ out) {
    extern __shared__ char dsm_raw[];
    uint32_t raw  = smem_u32(dsm_raw);
    uint32_t base = (raw + 127u) & ~127u;

    __shared__ unsigned long long s_part[4];
    __shared__ int s_act[DKS_];
    __shared__ int s_n;

    const int tid  = threadIdx.x;
    const int lane = tid & 31, w = tid >> 5;
    const int wm = w & 1, wn = w >> 1;            // 2 M-warps x 4 N-warps
    const int gt = wn * 32 + lane;                // index within wm-group (0..127)
    const int b  = blockIdx.x >> 3;
    const int t0 = (blockIdx.x & 7) * 256;
    const int o0 = blockIdx.y * 128;

    // ---- prologue: OR-reduce per-o masks -> active-d list ----
    if (tid < 128) {
        unsigned long long m = g_maskblk[o0 + tid];
#pragma unroll
        for (int s = 16; s > 0; s >>= 1)
            m |= __shfl_xor_sync(0xffffffffu, m, s);
        if (lane == 0) s_part[w] = m;
    }
    __syncthreads();
    if (tid == 0) {
        unsigned long long m = s_part[0] | s_part[1] | s_part[2] | s_part[3];
        int n = 0;
        for (int d = 0; d < DKS_; ++d)
            if (m & (1ull << d)) s_act[n++] = d;
        s_n = n;
    }
    __syncthreads();
    const int n_act = s_n;

    const uint32_t A0 = base;
    const uint32_t X0 = base + X_OFF;

    float acc[4][8][4];                           // [mi][p*2+nn][quad]
#pragma unroll
    for (int mi = 0; mi < 4; ++mi)
#pragma unroll
        for (int nf = 0; nf < 8; ++nf)
#pragma unroll
            for (int q = 0; q < 4; ++q) acc[mi][nf][q] = 0.f;

    // ldmatrix per-lane row/col offsets
    const uint32_t a_r = (lane & 7) + 8 * ((lane >> 3) & 1);
    const uint32_t a_c = (uint32_t)(lane >> 4) * 16;
    const uint32_t b_r = (lane & 7) + 8 * (lane >> 4);
    const uint32_t b_c = (uint32_t)((lane >> 3) & 1) * 16;

    for (int ic = 0; ic < 2 && n_act > 0; ++ic) {
        __syncthreads();    // all warps done with X (and A slots) of prev ic
        // ---- stage X tile (288 rows x 128 i): 4608 x 16B chunks ----
#pragma unroll
        for (int k = 0; k < 18; ++k) {
            int idx = tid + k * 256;
            int r = idx >> 4;
            int c = idx & 15;
            const __half* src = g_Xh
                + ((size_t)(b * TP_ + t0 + r) * 256 + ic * 128 + c * 8);
            cpa16(X0 + r * ROWB + c * 16, src);
        }
        // ---- stage A(act[0]) slot0 in same group as X ----
        stage_A_grp(A0, s_act[0], 0, o0, ic, wm, gt);
        CP_COMMIT();
        // ---- stage A(act[1]) slot1 (may stay in flight) ----
        if (n_act > 1) stage_A_grp(A0, s_act[1], 1, o0, ic, wm, gt);
        CP_COMMIT();     // always commit (empty group ok) -> invariant holds

#pragma unroll 1
        for (int j = 0; j < n_act; ++j) {
            const int d = s_act[j];
            CP_WAIT1();            // all groups except the latest are done
                                   // => X (ic) and A(j) are complete
            if (j == 0) __syncthreads();   // X visible to all
            else        GROUP_BAR(wm + 1); // group finished compute(j-1):
                                           // slot (j+2)%3 == (j-1)%3 is free

            if (j + 2 < n_act)     // overlap A(j+2) copy with compute(j, j+1)
                stage_A_grp(A0, s_act[j + 2], (j + 2) % 3, o0, ic, wm, gt);
            CP_COMMIT();           // always commit (keeps wait_group semantics)

            const uint32_t Ab = A0 + (uint32_t)(j % 3) * A_TS;
#pragma unroll
            for (int kk = 0; kk < 8; ++kk) {
                uint32_t ah[4][4];
#pragma unroll
                for (int mi = 0; mi < 4; ++mi) {
                    uint32_t ad = Ab + (wm * 64 + mi * 16 + a_r) * ROWB
                                + kk * 32 + a_c;
                    ldmx4(ah[mi], ad);
                }
#pragma unroll
                for (int p = 0; p < 4; ++p) {
                    uint32_t bh[4];
                    uint32_t bd = X0 + (wn * 64 + d + p * 16 + b_r) * ROWB
                                + kk * 32 + b_c;
                    ldmx4(bh, bd);
#pragma unroll
                    for (int mi = 0; mi < 4; ++mi)
#pragma unroll
                        for (int nn = 0; nn < 2; ++nn)
                            MMA(acc[mi][p * 2 + nn], ah[mi], bh[2 * nn], bh[2 * nn + 1]);
                }
            }
        }
        CP_WAIT0();   // drain tail groups before X/A slots are reused next ic
    }

    // ---- epilogue: add bias, store float2 ----
    const int g = lane >> 2, tg = lane & 3;
#pragma unroll
    for (int mi = 0; mi < 4; ++mi) {
        int o1 = o0 + wm * 64 + mi * 16 + g;
        float bv1 = bias[o1], bv2 = bias[o1 + 8];
        float* r1 = out + ((size_t)(b * O_ + o1)) * T_ + t0 + wn * 64 + tg * 2;
        float* r2 = r1 + 8 * T_;
#pragma unroll
        for (int nf = 0; nf < 8; ++nf) {
            float2 v1 = make_float2(acc[mi][nf][0] + bv1, acc[mi][nf][1] + bv1);
            float2 v2 = make_float2(acc[mi][nf][2] + bv2, acc[mi][nf][3] + bv2);
            *(float2*)(r1 + nf * 8) = v1;
            *(float2*)(r2 + nf * 8) = v2;
        }
    }
}

// ---------------------------------------------------------------------------
// Launch (2 kernels)
// ---------------------------------------------------------------------------
extern "C" void kernel_launch(void* const* d_in, const int* in_sizes, int n_in,
                              void* d_out, int out_size) {
    const float* x      = (const float*)d_in[0];
    const float* weight = (const float*)d_in[1];
    const float* P      = (const float*)d_in[2];
    const float* bias   = (const float*)d_in[3];
    float* out          = (float*)d_out;

    prep<<<4096 + 256, 256>>>(x, weight, P);

    cudaFuncSetAttribute(conv_mma, cudaFuncAttributeMaxDynamicSharedMemorySize, DSMEM);
    conv_mma<<<dim3(64, 2), 256, DSMEM>>>(bias, out);
}

// round 17
// speedup vs baseline: 1.2838x; 1.2838x over previous
#include <cuda_runtime.h>
#include <cuda_fp16.h>
#include <cstdint>

// ---------------------------------------------------------------------------
// Dcls1d via mma.sync (HMMA) fp16 GEMM, ACTIVE-d COMPACTION.
//   out[b,o,t] = bias[o] + sum_{d,i} K2[d,o,i] * x[b,i,t+d-16]
//   K2 and X single fp16 (validated error ~2.9e-4 rel l2). fp32 accum.
// R17: vectorized xsplit (float4 loads, half2 stores, 1024 blocks);
//      conv = R15 (16 warps, 32x64, 3-slot A pipeline, wait_group<=1)
//      with X(0) staging hoisted ahead of the mask prologue.
// ---------------------------------------------------------------------------

#define B_   8
#define C_   256
#define T_   2048
#define O_   256
#define DKS_ 33
#define KC_  16
#define TP_  2080   // 16 + 2048 + 16 padded time rows

__device__ __align__(16) __half g_Kh[DKS_ * O_ * C_];   // [d][o][i], fp16
__device__ __align__(16) __half g_Xh[B_ * TP_ * C_];    // [b][t+16][i], fp16
__device__ unsigned long long g_maskblk[O_];            // per-o nonzero mask

// ---- PTX helpers -----------------------------------------------------------
__device__ __forceinline__ uint32_t smem_u32(const void* p) {
    uint32_t a;
    asm("{ .reg .u64 t; cvta.to.shared.u64 t, %1; cvt.u32.u64 %0, t; }"
        : "=r"(a) : "l"(p));
    return a;
}
__device__ __forceinline__ void cpa16(uint32_t dst, const void* src) {
    asm volatile("cp.async.ca.shared.global [%0], [%1], 16;" :: "r"(dst), "l"(src));
}
#define CP_COMMIT() asm volatile("cp.async.commit_group;" ::: "memory")
#define CP_WAIT0()  asm volatile("cp.async.wait_group 0;" ::: "memory")
#define CP_WAIT1()  asm volatile("cp.async.wait_group 1;" ::: "memory")
#define GROUP_BAR(id) asm volatile("bar.sync %0, 128;" :: "r"(id) : "memory")

__device__ __forceinline__ void ldmx4(uint32_t* r, uint32_t addr) {
    asm volatile("ldmatrix.sync.aligned.m8n8.x4.shared.b16 {%0,%1,%2,%3}, [%4];"
                 : "=r"(r[0]), "=r"(r[1]), "=r"(r[2]), "=r"(r[3]) : "r"(addr));
}
#define MMA(dv, a, b0v, b1v)                                                   \
    asm volatile("mma.sync.aligned.m16n8k16.row.col.f32.f16.f16.f32 "          \
                 "{%0,%1,%2,%3},{%4,%5,%6,%7},{%8,%9},{%0,%1,%2,%3};"          \
                 : "+f"((dv)[0]), "+f"((dv)[1]), "+f"((dv)[2]), "+f"((dv)[3])  \
                 : "r"((a)[0]), "r"((a)[1]), "r"((a)[2]), "r"((a)[3]),         \
                   "r"(b0v), "r"(b1v))

// ---------------------------------------------------------------------------
// Fused prep.
//  blocks [0,1024): xsplit — 8 b x 8 i-stripes(32) x 16 t-tiles(128), 256 thr.
//    float4 loads -> fp32 smem transpose -> half2 stores.
//  blocks [1024,1280): build K2 (gather form) + per-o masks.
// ---------------------------------------------------------------------------
__global__ void prep(const float* __restrict__ x,
                     const float* __restrict__ w,
                     const float* __restrict__ P) {
    const int tid = threadIdx.x;

    if (blockIdx.x < 1024) {
        __shared__ float sm[32][132];             // [i][t], padded
        int blk = blockIdx.x;
        int t0 = (blk & 15) * 128;
        int i0 = ((blk >> 4) & 7) * 32;
        int b  = blk >> 7;

        // ---- load 32 i-rows x 128 t as float4 (1024 f4, 4/thread) ----
        int f4c = tid & 31;                       // float4 column (0..31)
        int r0  = tid >> 5;                       // row 0..7
#pragma unroll
        for (int k = 0; k < 4; ++k) {
            int i = r0 + k * 8;
            const float4* src = (const float4*)(x
                + ((size_t)(b * C_ + i0 + i) * T_ + t0)) + f4c;
            float4 v = *src;
            sm[i][f4c * 4 + 0] = v.x;
            sm[i][f4c * 4 + 1] = v.y;
            sm[i][f4c * 4 + 2] = v.z;
            sm[i][f4c * 4 + 3] = v.w;
        }

        // ---- zero pads (blocks covering t-tile 0 / 15 handle them) ----
        __half2* Xh2 = (__half2*)g_Xh;
        if ((blk & 15) == 0) {
            // pad rows [0,16): 16 t x 16 half2 = 256 half2, 1 per thread
            int r = tid >> 4, p = tid & 15;
            Xh2[((size_t)b * TP_ + r) * 128 + (i0 >> 1) + p] =
                __floats2half2_rn(0.f, 0.f);
        } else if ((blk & 15) == 15) {
            int r = tid >> 4, p = tid & 15;
            Xh2[((size_t)b * TP_ + (TP_ - 16 + r)) * 128 + (i0 >> 1) + p] =
                __floats2half2_rn(0.f, 0.f);
        }
        __syncthreads();

        // ---- transposed half2 stores: 128 t x 16 i-pairs ----
        int p  = tid & 15;                        // i-pair
        int tq = tid >> 4;                        // t base (0..15)
#pragma unroll
        for (int k = 0; k < 8; ++k) {
            int t = tq + k * 16;
            __half2 h = __floats2half2_rn(sm[2 * p][t], sm[2 * p + 1][t]);
            Xh2[((size_t)b * TP_ + t0 + t + 16) * 128 + (i0 >> 1) + p] = h;
        }
    } else {
        __shared__ unsigned long long s_m[8];
        // ---- build_k2 (gather form, no local memory) ----
        int bk = blockIdx.x - 1024;               // out-channel o
        int oi = bk * 256 + tid;                  // tid = input channel i
        const float* Prow  = P + (size_t)oi * KC_;
        const float* P0row = P + (size_t)tid * KC_;  // out-channel 0 (frac src)
        const float* Wrow  = w + (size_t)oi * KC_;

        int   pi[KC_];
        float c1[KC_], c2[KC_];
#pragma unroll
        for (int k = 0; k < KC_; ++k) {
            float pp  = Prow[k] + 16.f;
            pi[k]     = (int)floorf(pp);
            float pp0 = P0row[k] + 16.f;
            float fr  = pp0 - floorf(pp0);
            float wv  = Wrow[k];
            c1[k] = wv * (1.f - fr);
            c2[k] = wv * fr;
        }
        unsigned long long bits = 0ull;
#pragma unroll
        for (int d = 0; d < DKS_; ++d) {
            float v = 0.f;
#pragma unroll
            for (int k = 0; k < KC_; ++k) {
                if (pi[k] == d)     v += c1[k];
                if (pi[k] + 1 == d) v += c2[k];
            }
            if (v != 0.f) bits |= 1ull << d;
            g_Kh[(size_t)(d * O_ + bk) * C_ + tid] = __float2half(v);
        }
#pragma unroll
        for (int s = 16; s > 0; s >>= 1)
            bits |= __shfl_xor_sync(0xffffffffu, bits, s);
        if ((tid & 31) == 0) s_m[tid >> 5] = bits;
        __syncthreads();
        if (tid == 0) {
            unsigned long long m = 0ull;
#pragma unroll
            for (int q = 0; q < 8; ++q) m |= s_m[q];
            g_maskblk[bk] = m;
        }
    }
}

// ---------------------------------------------------------------------------
// GEMM kernel (R15-proven config).
// Block: 128 o x 256 t, 512 threads (16 warps: 4Mx4N, warp = 32 o x 64 t).
// ic-chunk = 128 i (2 chunks). smem rows 272B (conflict-free LDSM).
//   A (K2[d]): 128 x 128 i fp16, 3 slots; wm-group stages/syncs its 32 rows.
//   X: 288 x 128 i fp16 (per-ic, block barrier).
// cp.async depth 2 (wait_group<=1): A(j+1) in flight during compute(j).
// ---------------------------------------------------------------------------
#define ROWB   272u
#define A_TS   34816u      // one A slot (128*272)
#define X_OFF  (3u * 34816u)        // 104448
#define X_TS   78336u      // X tensor (288*272)
#define DSMEM  (104448u + 78336u + 128u)   // ~183 KB

__device__ __forceinline__ void stage_A_grp(uint32_t A0, int d, int slot,
                                            int o0, int ic, int wm, int gt) {
    uint32_t Ab = A0 + (uint32_t)slot * A_TS;
#pragma unroll
    for (int k = 0; k < 4; ++k) {
        int idx = gt + k * 128;                  // 512 chunks (32r x 16c)
        int r   = (idx >> 4) & 31;
        int c   = idx & 15;
        int row = wm * 32 + r;
        const __half* src = g_Kh
            + ((size_t)(d * 256 + o0 + row) * 256 + ic * 128 + c * 8);
        cpa16(Ab + row * ROWB + c * 16, src);
    }
}

__device__ __forceinline__ void stage_X(uint32_t X0, int b, int t0, int ic, int tid) {
#pragma unroll
    for (int k = 0; k < 9; ++k) {
        int idx = tid + k * 512;
        int r = idx >> 4;
        int c = idx & 15;
        const __half* src = g_Xh
            + ((size_t)(b * TP_ + t0 + r) * 256 + ic * 128 + c * 8);
        cpa16(X0 + r * ROWB + c * 16, src);
    }
}

__global__ __launch_bounds__(512, 1)
void conv_mma(const float* __restrict__ bias, float* __restrict__ out) {
    extern __shared__ char dsm_raw[];
    uint32_t raw  = smem_u32(dsm_raw);
    uint32_t base = (raw + 127u) & ~127u;

    __shared__ unsigned long long s_part[4];
    __shared__ int s_act[DKS_];
    __shared__ int s_n;

    const int tid  = threadIdx.x;
    const int lane = tid & 31, w = tid >> 5;
    const int wm = w & 3, wn = w >> 2;            // 4 M-warps x 4 N-warps
    const int gt = wn * 32 + lane;                // index within wm-group
    const int b  = blockIdx.x >> 3;
    const int t0 = (blockIdx.x & 7) * 256;
    const int o0 = blockIdx.y * 128;

    const uint32_t A0 = base;
    const uint32_t X0 = base + X_OFF;

    // ---- X(0) staging first (independent of the mask prologue) ----
    stage_X(X0, b, t0, 0, tid);

    // ---- prologue: OR-reduce per-o masks -> active-d list ----
    if (tid < 128) {
        unsigned long long m = g_maskblk[o0 + tid];
#pragma unroll
        for (int s = 16; s > 0; s >>= 1)
            m |= __shfl_xor_sync(0xffffffffu, m, s);
        if (lane == 0) s_part[w] = m;
    }
    __syncthreads();
    if (tid == 0) {
        unsigned long long m = s_part[0] | s_part[1] | s_part[2] | s_part[3];
        int n = 0;
        for (int d = 0; d < DKS_; ++d)
            if (m & (1ull << d)) s_act[n++] = d;
        s_n = n;
    }
    __syncthreads();
    const int n_act = s_n;

    float acc[2][8][4];
#pragma unroll
    for (int mi = 0; mi < 2; ++mi)
#pragma unroll
        for (int nf = 0; nf < 8; ++nf)
#pragma unroll
            for (int q = 0; q < 4; ++q) acc[mi][nf][q] = 0.f;

    // ldmatrix per-lane row/col offsets
    const uint32_t a_r = (lane & 7) + 8 * ((lane >> 3) & 1);
    const uint32_t a_c = (uint32_t)(lane >> 4) * 16;
    const uint32_t b_r = (lane & 7) + 8 * (lane >> 4);
    const uint32_t b_c = (uint32_t)((lane >> 3) & 1) * 16;

    for (int ic = 0; ic < 2 && n_act > 0; ++ic) {
        if (ic > 0) {
            __syncthreads();    // all warps done with X (and A slots)
            stage_X(X0, b, t0, ic, tid);
        }
        // ---- stage A(act[0]) slot0 in same group as X ----
        stage_A_grp(A0, s_act[0], 0, o0, ic, wm, gt);
        CP_COMMIT();
        // ---- stage A(act[1]) slot1 (may stay in flight) ----
        if (n_act > 1) stage_A_grp(A0, s_act[1], 1, o0, ic, wm, gt);
        CP_COMMIT();     // always commit (empty group ok) -> invariant holds

#pragma unroll 1
        for (int j = 0; j < n_act; ++j) {
            const int d = s_act[j];
            CP_WAIT1();            // all groups except the latest are done
                                   // => X (ic) and A(j) are complete
            if (j == 0) __syncthreads();   // X visible to all
            else        GROUP_BAR(wm + 1); // group finished compute(j-1):
                                           // slot (j+2)%3 == (j-1)%3 is free

            if (j + 2 < n_act)     // overlap A(j+2) copy with compute(j, j+1)
                stage_A_grp(A0, s_act[j + 2], (j + 2) % 3, o0, ic, wm, gt);
            CP_COMMIT();           // always commit (keeps wait_group semantics)

            const uint32_t Ab = A0 + (uint32_t)(j % 3) * A_TS;
#pragma unroll
            for (int kk = 0; kk < 8; ++kk) {
                uint32_t ah[2][4];
#pragma unroll
                for (int mi = 0; mi < 2; ++mi) {
                    uint32_t ad = Ab + (wm * 32 + mi * 16 + a_r) * ROWB
                                + kk * 32 + a_c;
                    ldmx4(ah[mi], ad);
                }
#pragma unroll
                for (int p = 0; p < 4; ++p) {
                    uint32_t bh[4];
                    uint32_t bd = X0 + (wn * 64 + d + p * 16 + b_r) * ROWB
                                + kk * 32 + b_c;
                    ldmx4(bh, bd);
#pragma unroll
                    for (int mi = 0; mi < 2; ++mi)
#pragma unroll
                        for (int nn = 0; nn < 2; ++nn)
                            MMA(acc[mi][p * 2 + nn], ah[mi], bh[2 * nn], bh[2 * nn + 1]);
                }
            }
        }
        CP_WAIT0();   // drain tail groups before X/A slots are reused next ic
    }
    if (n_act == 0) CP_WAIT0();    // safety: never exit with pending cp.async

    // ---- epilogue: add bias, store float2 ----
    const int g = lane >> 2, tg = lane & 3;
#pragma unroll
    for (int mi = 0; mi < 2; ++mi) {
        int o1 = o0 + wm * 32 + mi * 16 + g;
        float bv1 = bias[o1], bv2 = bias[o1 + 8];
        float* r1 = out + ((size_t)(b * O_ + o1)) * T_ + t0 + wn * 64 + tg * 2;
        float* r2 = r1 + 8 * T_;
#pragma unroll
        for (int nf = 0; nf < 8; ++nf) {
            float2 v1 = make_float2(acc[mi][nf][0] + bv1, acc[mi][nf][1] + bv1);
            float2 v2 = make_float2(acc[mi][nf][2] + bv2, acc[mi][nf][3] + bv2);
            *(float2*)(r1 + nf * 8) = v1;
            *(float2*)(r2 + nf * 8) = v2;
        }
    }
}

// ---------------------------------------------------------------------------
// Launch (2 kernels)
// ---------------------------------------------------------------------------
extern "C" void kernel_launch(void* const* d_in, const int* in_sizes, int n_in,
                              void* d_out, int out_size) {
    const float* x      = (const float*)d_in[0];
    const float* weight = (const float*)d_in[1];
    const float* P      = (const float*)d_in[2];
    const float* bias   = (const float*)d_in[3];
    float* out          = (float*)d_out;

    prep<<<1024 + 256, 256>>>(x, weight, P);

    cudaFuncSetAttribute(conv_mma, cudaFuncAttributeMaxDynamicSharedMemorySize, DSMEM);
    conv_mma<<<dim3(64, 2), 512, DSMEM>>>(bias, out);
}